// round 1
// baseline (speedup 1.0000x reference)
#include <cuda_runtime.h>
#include <cuda_bf16.h>

// social_stgcn_46462956208716
//
// Reference analysis: the network ends with
//     out = gcn_conv(h, edge_index, W2, b2)        # shape [16384, 1]
//     return jax.nn.log_softmax(out, axis=1)
// log_softmax over a length-1 axis is identically zero for any finite input
// (x - logsumexp([x]) == 0). All inputs are finite, so the reference output
// is exactly zeros of shape [16384, 1]. The entire GCN computation cancels.
//
// Therefore the optimal kernel writes out_size zero floats to d_out
// (which the harness poisons to 0xAA before timing).

__global__ void zero_out_kernel(float4* __restrict__ out, int n_vec4) {
    int i = blockIdx.x * blockDim.x + threadIdx.x;
    if (i < n_vec4) {
        out[i] = make_float4(0.f, 0.f, 0.f, 0.f);
    }
}

__global__ void zero_out_tail_kernel(float* __restrict__ out, int start, int n) {
    int i = start + blockIdx.x * blockDim.x + threadIdx.x;
    if (i < n) {
        out[i] = 0.f;
    }
}

extern "C" void kernel_launch(void* const* d_in, const int* in_sizes, int n_in,
                              void* d_out, int out_size) {
    (void)d_in; (void)in_sizes; (void)n_in;

    float* out = (float*)d_out;

    int n_vec4 = out_size / 4;        // 16384 / 4 = 4096 float4 stores
    int tail_start = n_vec4 * 4;

    if (n_vec4 > 0) {
        const int threads = 256;
        int blocks = (n_vec4 + threads - 1) / threads;   // 16 CTAs — one wave
        zero_out_kernel<<<blocks, threads>>>((float4*)out, n_vec4);
    }
    if (tail_start < out_size) {
        zero_out_tail_kernel<<<1, 128>>>(out, tail_start, out_size);
    }
}

// round 2
// speedup vs baseline: 1.0556x; 1.0556x over previous
#include <cuda_runtime.h>
#include <cuda_bf16.h>

// social_stgcn_46462956208716
//
// The reference ends with log_softmax over a length-1 axis:
//     out = gcn_conv(h, edge_index, W2, b2)   # [16384, 1]
//     return jax.nn.log_softmax(out, axis=1)  # x - logsumexp([x]) == 0
// For any finite input this is identically zero, and all inputs are finite
// (seeded Gaussians; degree norm guarded by where/max). So the full 2-layer
// GCN is algebraically annihilated: output = zeros([16384, 1]).
//
// Optimal kernel: one launch, write out_size zero floats. We are at the
// graph-replay + launch-latency floor; this version minimizes CTA count and
// guarantees a single graph node.

__global__ __launch_bounds__(1024, 1)
void zero_out_kernel(float* __restrict__ out, int out_size) {
    int i = blockIdx.x * blockDim.x + threadIdx.x;   // 0..4095
    int i4 = i * 4;
    if (i4 + 3 < out_size) {
        *reinterpret_cast<float4*>(out + i4) = make_float4(0.f, 0.f, 0.f, 0.f);
    } else {
        // tail (dead at runtime for out_size % 4 == 0, kept for generality)
        for (int j = i4; j < out_size; ++j) out[j] = 0.f;
    }
}

extern "C" void kernel_launch(void* const* d_in, const int* in_sizes, int n_in,
                              void* d_out, int out_size) {
    (void)d_in; (void)in_sizes; (void)n_in;

    float* out = (float*)d_out;

    // out_size = 16384 -> 4096 float4 stores -> 4 CTAs x 1024 threads, one wave.
    int n_vec4 = (out_size + 3) / 4;
    const int threads = 1024;
    int blocks = (n_vec4 + threads - 1) / threads;
    if (blocks < 1) blocks = 1;
    zero_out_kernel<<<blocks, threads>>>(out, out_size);
}